// round 9
// baseline (speedup 1.0000x reference)
#include <cuda_runtime.h>

// out[b, p, d] = x[b, p] * W[p, d] + bias[p, d]
// B=64, P=2000, D=512 (fp32). HBM-write-bound: 262MB out (~6.7TB/s achieved).
//
// Converged shape (R3/R8): thread = one (p,d4) float4 column x 8 batch rows,
// grid 1000x8x256. Swept: B_CHUNK {4:60.1, 8:40.0, 16:41.0}, TPB {128,256}~=,
// persistent grid 45.4 (HW scheduler wins), 256-bit stores 45.1 (lost MLP).
// FINAL A/B: store cache policy. All prior runs used .cs (evict-first).
// This run: default stores — hypothesis: L2 accumulates larger writeback
// batches per DRAM page; W/b re-reads are frequent enough to stay warm
// under LRU without the .cs shield.

#define B_DIM 64
#define P_DIM 2000
#define D_DIM 512
#define D4 (D_DIM / 4)              // 128
#define PD4 (P_DIM * D4)            // 256000
#define B_CHUNK 8                   // batches per thread
#define N_CHUNKS (B_DIM / B_CHUNK)  // 8

__global__ __launch_bounds__(256) void feature_expander_kernel(
    const float* __restrict__ x,      // [B, P]
    const float4* __restrict__ W,     // [P, D/4]
    const float4* __restrict__ bias,  // [P, D/4]
    float4* __restrict__ out)         // [B, P, D/4]
{
    int idx = blockIdx.x * blockDim.x + threadIdx.x;   // < PD4 always (1000*256)
    int p = idx >> 7;                                  // idx / 128
    int b0 = blockIdx.y * B_CHUNK;

    float4 w = __ldg(&W[idx]);
    float4 bv = __ldg(&bias[idx]);

    const float* xp = x + b0 * P_DIM + p;
    float4* op = out + (size_t)b0 * PD4 + idx;

    #pragma unroll
    for (int i = 0; i < B_CHUNK; i++) {
        float xv = __ldg(xp + i * P_DIM);
        float4 o;
        o.x = fmaf(xv, w.x, bv.x);
        o.y = fmaf(xv, w.y, bv.y);
        o.z = fmaf(xv, w.z, bv.z);
        o.w = fmaf(xv, w.w, bv.w);
        op[(size_t)i * PD4] = o;      // default store policy (A/B vs .cs)
    }
}

extern "C" void kernel_launch(void* const* d_in, const int* in_sizes, int n_in,
                              void* d_out, int out_size) {
    const float*  x  = (const float*)d_in[0];
    const float4* W  = (const float4*)d_in[1];
    const float4* bb = (const float4*)d_in[2];
    float4* out = (float4*)d_out;

    dim3 grid(PD4 / 256, N_CHUNKS);   // 1000 x 8
    feature_expander_kernel<<<grid, 256>>>(x, W, bb, out);
}

// round 10
// speedup vs baseline: 1.1584x; 1.1584x over previous
#include <cuda_runtime.h>

// out[b, p, d] = x[b, p] * W[p, d] + bias[p, d]
// B=64, P=2000, D=512 (fp32).
//
// FINAL — converged at the HBM write roofline: 262MB output / ~39us =
// ~6.7TB/s sustained pure writes (reads ~8.5MB, L2-resident).
//
// Every axis A/B'd on hardware:
//   B_CHUNK:      4->60.1us, 8->40.0us, 16->41.0us        (8 wins)
//   TPB:          128->40.4us, 256->40.0us                 (tie)
//   scheduling:   HW grid 40.0us, persistent 1184 45.4us   (HW wins)
//   access width: 128-bit 40.0us, 256-bit v8.f32 45.1us    (128-bit: MLP wins)
//   store policy: .cs 40.0us, default 45.6us               (.cs load-bearing:
//                 protects L2-resident W/b from the 262MB write stream)
//
// Shape: thread = one (p, d4) float4 column x 8 batch rows, grid 1000x8x256.
// W/b loaded once per thread (re-reads hit L2; W+b = 8MB resident). x loads
// are per-warp broadcasts (L1 hits). Streaming .cs stores.

#define B_DIM 64
#define P_DIM 2000
#define D_DIM 512
#define D4 (D_DIM / 4)              // 128
#define PD4 (P_DIM * D4)            // 256000
#define B_CHUNK 8                   // batches per thread
#define N_CHUNKS (B_DIM / B_CHUNK)  // 8

__global__ __launch_bounds__(256) void feature_expander_kernel(
    const float* __restrict__ x,      // [B, P]
    const float4* __restrict__ W,     // [P, D/4]
    const float4* __restrict__ bias,  // [P, D/4]
    float4* __restrict__ out)         // [B, P, D/4]
{
    int idx = blockIdx.x * blockDim.x + threadIdx.x;   // < PD4 always (1000*256)
    int p = idx >> 7;                                  // idx / 128
    int b0 = blockIdx.y * B_CHUNK;

    float4 w = __ldg(&W[idx]);
    float4 bv = __ldg(&bias[idx]);

    const float* xp = x + b0 * P_DIM + p;
    float4* op = out + (size_t)b0 * PD4 + idx;

    #pragma unroll
    for (int i = 0; i < B_CHUNK; i++) {
        float xv = __ldg(xp + i * P_DIM);
        float4 o;
        o.x = fmaf(xv, w.x, bv.x);
        o.y = fmaf(xv, w.y, bv.y);
        o.z = fmaf(xv, w.z, bv.z);
        o.w = fmaf(xv, w.w, bv.w);
        __stcs(op + (size_t)i * PD4, o);   // streaming store (evict-first)
    }
}

extern "C" void kernel_launch(void* const* d_in, const int* in_sizes, int n_in,
                              void* d_out, int out_size) {
    const float*  x  = (const float*)d_in[0];
    const float4* W  = (const float4*)d_in[1];
    const float4* bb = (const float4*)d_in[2];
    float4* out = (float4*)d_out;

    dim3 grid(PD4 / 256, N_CHUNKS);   // 1000 x 8
    feature_expander_kernel<<<grid, 256>>>(x, W, bb, out);
}